// round 2
// baseline (speedup 1.0000x reference)
#include <cuda_runtime.h>
#include <math.h>

#define NMAX 100000
#define EMAX 1600000
#define KDIM 128   // inner dim for both GEMMs (Fin = Hid = 128)

// ---------------- scratch (static device globals; no allocation) ------------
__device__ __align__(16) float d_g1[(size_t)NMAX * 128]; // (x@W1)*dinv
__device__ __align__(16) float d_h1[(size_t)NMAX * 128]; // layer-1 output (post relu)
__device__ __align__(16) float d_g2[(size_t)NMAX * 64];  // (h1@W2)*dinv
__device__ float d_dinv[NMAX];
__device__ int   d_counts[NMAX];
__device__ int   d_offsets[NMAX];
__device__ int   d_cursor[NMAX];
__device__ int   d_csr[EMAX];

// ---------------- CSR build -------------------------------------------------
__global__ void k_zero(int n) {
    int i = blockIdx.x * blockDim.x + threadIdx.x;
    if (i < n) d_counts[i] = 0;
}

__global__ void k_count(const int* __restrict__ ei, int E) {
    int e = blockIdx.x * blockDim.x + threadIdx.x;
    if (e < E) {
        int dst = ei[(size_t)E + e];
        atomicAdd(&d_counts[dst], 1);
    }
}

// single-block exclusive scan of counts -> offsets (+cursor copy, +dinv)
__global__ void k_scan(int n) {
    __shared__ int s[1024];
    int tid = threadIdx.x;
    int run = 0;
    for (int base = 0; base < n; base += 1024) {
        int i = base + tid;
        int v = (i < n) ? d_counts[i] : 0;
        s[tid] = v;
        __syncthreads();
        for (int d = 1; d < 1024; d <<= 1) {
            int t = (tid >= d) ? s[tid - d] : 0;
            __syncthreads();
            s[tid] += t;
            __syncthreads();
        }
        int incl  = s[tid];
        int total = s[1023];
        if (i < n) {
            int off = run + incl - v;
            d_offsets[i] = off;
            d_cursor[i]  = off;
            d_dinv[i]    = rsqrtf((float)(1 + v)); // deg = 1 (self-loop) + in-degree
        }
        run += total;
        __syncthreads(); // protect s[] before next chunk overwrites
    }
}

__global__ void k_fill(const int* __restrict__ ei, int E) {
    int e = blockIdx.x * blockDim.x + threadIdx.x;
    if (e < E) {
        int src = ei[e];
        int dst = ei[(size_t)E + e];
        int p = atomicAdd(&d_cursor[dst], 1);
        d_csr[p] = src;
    }
}

// ---------------- GEMM: G = (A[M,128] @ W[128,BN]) * dinv[row] --------------
template <int BN, int NT>
__global__ void __launch_bounds__(NT)
k_gemm(const float* __restrict__ A, const float* __restrict__ W,
       float* __restrict__ G, int M) {
    constexpr int BM = 64, BK = 16, TM = 8, TN = 4, K = KDIM;
    static_assert(NT == (BM / TM) * (BN / TN), "thread count mismatch");
    __shared__ __align__(16) float As[BK][BM];
    __shared__ __align__(16) float Bs[BK][BN];

    const int tid  = threadIdx.x;
    const int r0   = blockIdx.x * BM;
    const int tcol = tid % (BN / TN);
    const int trow = tid / (BN / TN);

    float acc[TM][TN] = {};
    constexpr int A_F4 = (BM * BK) / (NT * 4);
    constexpr int B_F4 = (BK * BN) / (NT * 4);

    for (int kt = 0; kt < K; kt += BK) {
        #pragma unroll
        for (int i = 0; i < A_F4; i++) {
            int idx = tid + i * NT;
            int ar  = idx / (BK / 4);
            int ac  = idx % (BK / 4);
            float4 v = make_float4(0.f, 0.f, 0.f, 0.f);
            int row = r0 + ar;
            if (row < M)
                v = *reinterpret_cast<const float4*>(A + (size_t)row * K + kt + ac * 4);
            As[ac * 4 + 0][ar] = v.x;
            As[ac * 4 + 1][ar] = v.y;
            As[ac * 4 + 2][ar] = v.z;
            As[ac * 4 + 3][ar] = v.w;
        }
        #pragma unroll
        for (int i = 0; i < B_F4; i++) {
            int idx = tid + i * NT;
            int br  = idx / (BN / 4);
            int bc  = idx % (BN / 4);
            *reinterpret_cast<float4*>(&Bs[br][bc * 4]) =
                *reinterpret_cast<const float4*>(W + (size_t)(kt + br) * BN + bc * 4);
        }
        __syncthreads();

        #pragma unroll
        for (int k = 0; k < BK; k++) {
            float4 a0 = *reinterpret_cast<const float4*>(&As[k][trow * TM]);
            float4 a1 = *reinterpret_cast<const float4*>(&As[k][trow * TM + 4]);
            float4 b0 = *reinterpret_cast<const float4*>(&Bs[k][tcol * TN]);
            float rm[TM] = {a0.x, a0.y, a0.z, a0.w, a1.x, a1.y, a1.z, a1.w};
            float rn[TN] = {b0.x, b0.y, b0.z, b0.w};
            #pragma unroll
            for (int i = 0; i < TM; i++)
                #pragma unroll
                for (int j = 0; j < TN; j++)
                    acc[i][j] += rm[i] * rn[j];
        }
        __syncthreads();
    }

    #pragma unroll
    for (int i = 0; i < TM; i++) {
        int row = r0 + trow * TM + i;
        if (row < M) {
            float s = d_dinv[row];
            float4 o;
            o.x = acc[i][0] * s;
            o.y = acc[i][1] * s;
            o.z = acc[i][2] * s;
            o.w = acc[i][3] * s;
            *reinterpret_cast<float4*>(G + (size_t)row * BN + tcol * TN) = o;
        }
    }
}

// ---------------- aggregation: out[i] = relu(dinv[i]*(g[i]+sum g[src]) + b) -
template <int F>
__global__ void k_agg(const float* __restrict__ g, const float* __restrict__ bias,
                      float* __restrict__ out, int n) {
    constexpr int V = F / 32; // floats per lane (4 for F=128, 2 for F=64)
    int w = (blockIdx.x * blockDim.x + threadIdx.x) >> 5;
    if (w >= n) return;
    int lane = threadIdx.x & 31;

    float acc[V];
    const float* self = g + (size_t)w * F + lane * V;
    if constexpr (V == 4) {
        float4 t = *reinterpret_cast<const float4*>(self);
        acc[0] = t.x; acc[1] = t.y; acc[2] = t.z; acc[3] = t.w;
    } else {
        float2 t = *reinterpret_cast<const float2*>(self);
        acc[0] = t.x; acc[1] = t.y;
    }

    int start = d_offsets[w];
    int cnt   = d_counts[w];
    for (int j = 0; j < cnt; j += 8) {
        int idx[8];
        #pragma unroll
        for (int u = 0; u < 8; u++) {
            int jj = j + u;
            idx[u] = (jj < cnt) ? d_csr[start + jj] : w; // dummy = self row (L1-hot)
        }
        if constexpr (V == 4) {
            float4 t[8];
            #pragma unroll
            for (int u = 0; u < 8; u++)
                t[u] = *reinterpret_cast<const float4*>(g + (size_t)idx[u] * F + lane * 4);
            #pragma unroll
            for (int u = 0; u < 8; u++)
                if (j + u < cnt) {
                    acc[0] += t[u].x; acc[1] += t[u].y;
                    acc[2] += t[u].z; acc[3] += t[u].w;
                }
        } else {
            float2 t[8];
            #pragma unroll
            for (int u = 0; u < 8; u++)
                t[u] = *reinterpret_cast<const float2*>(g + (size_t)idx[u] * F + lane * 2);
            #pragma unroll
            for (int u = 0; u < 8; u++)
                if (j + u < cnt) {
                    acc[0] += t[u].x; acc[1] += t[u].y;
                }
        }
    }

    float dv = d_dinv[w];
    float r[V];
    #pragma unroll
    for (int v = 0; v < V; v++) {
        float val = acc[v] * dv + __ldg(&bias[lane * V + v]);
        r[v] = val > 0.f ? val : 0.f;
    }
    float* o = out + (size_t)w * F + lane * V;
    if constexpr (V == 4) {
        *reinterpret_cast<float4*>(o) = make_float4(r[0], r[1], r[2], r[3]);
    } else {
        *reinterpret_cast<float2*>(o) = make_float2(r[0], r[1]);
    }
}

// ---------------- launch -----------------------------------------------------
extern "C" void kernel_launch(void* const* d_in, const int* in_sizes, int n_in,
                              void* d_out, int out_size) {
    const float* x  = (const float*)d_in[0];
    const int*   ei = (const int*)d_in[1];   // JAX downcasts int64 -> int32
    const float* W1 = (const float*)d_in[2];
    const float* b1 = (const float*)d_in[3];
    const float* W2 = (const float*)d_in[4];
    const float* b2 = (const float*)d_in[5];
    float* out = (float*)d_out;

    const int M = in_sizes[0] / 128;  // 100000 nodes
    const int E = in_sizes[1] / 2;    // 1600000 edges

    float *g1, *h1, *g2;
    cudaGetSymbolAddress((void**)&g1, d_g1);
    cudaGetSymbolAddress((void**)&h1, d_h1);
    cudaGetSymbolAddress((void**)&g2, d_g2);

    // CSR build (shared by both layers)
    k_zero <<<(M + 255) / 256, 256>>>(M);
    k_count<<<(E + 255) / 256, 256>>>(ei, E);
    k_scan <<<1, 1024>>>(M);
    k_fill <<<(E + 255) / 256, 256>>>(ei, E);

    // layer 1: g1 = (x@W1)*dinv ; h1 = relu(dinv*(g1_self + gather) + b1)
    k_gemm<128, 256><<<(M + 63) / 64, 256>>>(x, W1, g1, M);
    k_agg<128><<<((M * 32) + 255) / 256, 256>>>(g1, b1, h1, M);

    // layer 2: g2 = (h1@W2)*dinv ; out = relu(dinv*(g2_self + gather) + b2)
    k_gemm<64, 128><<<(M + 63) / 64, 128>>>(h1, W2, g2, M);
    k_agg<64><<<((M * 32) + 255) / 256, 256>>>(g2, b2, out, M);
}

// round 3
// speedup vs baseline: 1.0741x; 1.0741x over previous
#include <cuda_runtime.h>
#include <math.h>

#define NMAX 100000
#define EMAX 1600000
#define KDIM 128   // inner dim for both GEMMs (Fin = Hid = 128)

// ---------------- scratch (static device globals; no allocation) ------------
__device__ __align__(16) float d_g1[(size_t)NMAX * 128]; // x@W1 (unscaled)
__device__ __align__(16) float d_h1[(size_t)NMAX * 128]; // layer-1 output (post relu)
__device__ __align__(16) float d_g2[(size_t)NMAX * 64];  // h1@W2 (unscaled)
__device__ float d_dinv[NMAX];
__device__ int   d_counts[NMAX];
__device__ int   d_offsets[NMAX];
__device__ int   d_cursor[NMAX];
__device__ int   d_csr[EMAX];

// ---------------- CSR build -------------------------------------------------
__global__ void k_zero(int n) {
    int i = blockIdx.x * blockDim.x + threadIdx.x;
    if (i < n) d_counts[i] = 0;
}

__global__ void k_count(const int* __restrict__ ei, int E) {
    int e = blockIdx.x * blockDim.x + threadIdx.x;
    if (e < E) {
        int dst = ei[(size_t)E + e];
        atomicAdd(&d_counts[dst], 1);
    }
}

// single-block scan, warp-shuffle based (3 barriers per 1024-chunk)
__global__ void k_scan(int n) {
    __shared__ int wsum[32];
    int tid  = threadIdx.x;
    int lane = tid & 31;
    int wid  = tid >> 5;
    int run  = 0;
    for (int base = 0; base < n; base += 1024) {
        int i = base + tid;
        int v = (i < n) ? d_counts[i] : 0;
        // warp inclusive scan
        int x = v;
        #pragma unroll
        for (int d = 1; d < 32; d <<= 1) {
            int t = __shfl_up_sync(0xffffffffu, x, d);
            if (lane >= d) x += t;
        }
        if (lane == 31) wsum[wid] = x;
        __syncthreads();
        if (wid == 0) {
            int s = wsum[lane];
            #pragma unroll
            for (int d = 1; d < 32; d <<= 1) {
                int t = __shfl_up_sync(0xffffffffu, s, d);
                if (lane >= d) s += t;
            }
            wsum[lane] = s;
        }
        __syncthreads();
        int warp_prefix = (wid > 0) ? wsum[wid - 1] : 0;
        int total       = wsum[31];
        int incl        = run + warp_prefix + x;
        if (i < n) {
            int off = incl - v;
            d_offsets[i] = off;
            d_cursor[i]  = off;
            d_dinv[i]    = rsqrtf((float)(1 + v)); // deg = self-loop + in-degree
        }
        run += total;
        __syncthreads(); // protect wsum before next chunk overwrites
    }
}

__global__ void k_fill(const int* __restrict__ ei, int E) {
    int e = blockIdx.x * blockDim.x + threadIdx.x;
    if (e < E) {
        int src = ei[e];
        int dst = ei[(size_t)E + e];
        int p = atomicAdd(&d_cursor[dst], 1);
        d_csr[p] = src;
    }
}

// ---------------- GEMM: G = A[M,128] @ W[128,BN]  (unscaled) ----------------
// BM=128, BK=16, TM=8; NT=256. BN/TN must equal 16.
template <int BN, int TN>
__global__ void __launch_bounds__(256)
k_gemm(const float* __restrict__ A, const float* __restrict__ W,
       float* __restrict__ G, int M) {
    constexpr int BM = 128, BK = 16, TM = 8, NT = 256, K = KDIM;
    static_assert(BN / TN == 16, "layout");
    __shared__ __align__(16) float As[BK][BM];
    __shared__ __align__(16) float Bs[BK][BN];

    const int tid  = threadIdx.x;
    const int r0   = blockIdx.x * BM;
    const int tcol = tid & 15;        // 0..15
    const int trow = tid >> 4;        // 0..15

    float acc[TM][TN] = {};
    constexpr int A_F4 = (BM * BK) / (NT * 4);  // 2
    constexpr int B_F4 = (BK * BN) / (NT * 4);  // 2 or 1

    for (int kt = 0; kt < K; kt += BK) {
        #pragma unroll
        for (int i = 0; i < A_F4; i++) {
            int idx = tid + i * NT;
            int ar  = idx >> 2;          // /(BK/4)
            int ac  = idx & 3;
            float4 v = make_float4(0.f, 0.f, 0.f, 0.f);
            int row = r0 + ar;
            if (row < M)
                v = *reinterpret_cast<const float4*>(A + (size_t)row * K + kt + ac * 4);
            As[ac * 4 + 0][ar] = v.x;
            As[ac * 4 + 1][ar] = v.y;
            As[ac * 4 + 2][ar] = v.z;
            As[ac * 4 + 3][ar] = v.w;
        }
        #pragma unroll
        for (int i = 0; i < B_F4; i++) {
            int idx = tid + i * NT;
            int br  = idx / (BN / 4);
            int bc  = idx % (BN / 4);
            *reinterpret_cast<float4*>(&Bs[br][bc * 4]) =
                *reinterpret_cast<const float4*>(W + (size_t)(kt + br) * BN + bc * 4);
        }
        __syncthreads();

        #pragma unroll
        for (int k = 0; k < BK; k++) {
            float rm[TM], rn[TN];
            float4 a0 = *reinterpret_cast<const float4*>(&As[k][trow * TM]);
            float4 a1 = *reinterpret_cast<const float4*>(&As[k][trow * TM + 4]);
            rm[0]=a0.x; rm[1]=a0.y; rm[2]=a0.z; rm[3]=a0.w;
            rm[4]=a1.x; rm[5]=a1.y; rm[6]=a1.z; rm[7]=a1.w;
            float4 b0 = *reinterpret_cast<const float4*>(&Bs[k][tcol * TN]);
            rn[0]=b0.x; rn[1]=b0.y; rn[2]=b0.z; rn[3]=b0.w;
            if constexpr (TN == 8) {
                float4 b1 = *reinterpret_cast<const float4*>(&Bs[k][tcol * TN + 4]);
                rn[4]=b1.x; rn[5]=b1.y; rn[6]=b1.z; rn[7]=b1.w;
            }
            #pragma unroll
            for (int i = 0; i < TM; i++)
                #pragma unroll
                for (int j = 0; j < TN; j++)
                    acc[i][j] += rm[i] * rn[j];
        }
        __syncthreads();
    }

    #pragma unroll
    for (int i = 0; i < TM; i++) {
        int row = r0 + trow * TM + i;
        if (row < M) {
            float* o = G + (size_t)row * BN + tcol * TN;
            #pragma unroll
            for (int j = 0; j < TN; j += 4)
                *reinterpret_cast<float4*>(o + j) =
                    make_float4(acc[i][j], acc[i][j+1], acc[i][j+2], acc[i][j+3]);
        }
    }
}

// ------ aggregation: out[i] = relu(dinv[i]*(Σ dinv[s]g[s] + dinv[i]g[i]) + b)
template <int F>
__global__ void k_agg(const float* __restrict__ g, const float* __restrict__ bias,
                      float* __restrict__ out, int n) {
    constexpr int V = F / 32; // floats per lane (4 for F=128, 2 for F=64)
    int w = (blockIdx.x * blockDim.x + threadIdx.x) >> 5;
    if (w >= n) return;
    int lane = threadIdx.x & 31;

    float dv = d_dinv[w];
    float acc[V];
    const float* self = g + (size_t)w * F + lane * V;
    if constexpr (V == 4) {
        float4 t = *reinterpret_cast<const float4*>(self);
        acc[0] = t.x * dv; acc[1] = t.y * dv; acc[2] = t.z * dv; acc[3] = t.w * dv;
    } else {
        float2 t = *reinterpret_cast<const float2*>(self);
        acc[0] = t.x * dv; acc[1] = t.y * dv;
    }

    int start = d_offsets[w];
    int cnt   = d_counts[w];
    for (int j = 0; j < cnt; j += 8) {
        int idx[8];
        float wgt[8];
        #pragma unroll
        for (int u = 0; u < 8; u++) {
            int jj = j + u;
            idx[u] = (jj < cnt) ? d_csr[start + jj] : w; // dummy = self row
        }
        #pragma unroll
        for (int u = 0; u < 8; u++)
            wgt[u] = d_dinv[idx[u]];  // warp-uniform 4B load, L1/L2-hot
        if constexpr (V == 4) {
            float4 t[8];
            #pragma unroll
            for (int u = 0; u < 8; u++)
                t[u] = *reinterpret_cast<const float4*>(g + (size_t)idx[u] * F + lane * 4);
            #pragma unroll
            for (int u = 0; u < 8; u++)
                if (j + u < cnt) {
                    acc[0] += t[u].x * wgt[u]; acc[1] += t[u].y * wgt[u];
                    acc[2] += t[u].z * wgt[u]; acc[3] += t[u].w * wgt[u];
                }
        } else {
            float2 t[8];
            #pragma unroll
            for (int u = 0; u < 8; u++)
                t[u] = *reinterpret_cast<const float2*>(g + (size_t)idx[u] * F + lane * 2);
            #pragma unroll
            for (int u = 0; u < 8; u++)
                if (j + u < cnt) {
                    acc[0] += t[u].x * wgt[u]; acc[1] += t[u].y * wgt[u];
                }
        }
    }

    float r[V];
    #pragma unroll
    for (int v = 0; v < V; v++) {
        float val = acc[v] * dv + __ldg(&bias[lane * V + v]);
        r[v] = val > 0.f ? val : 0.f;
    }
    float* o = out + (size_t)w * F + lane * V;
    if constexpr (V == 4) {
        *reinterpret_cast<float4*>(o) = make_float4(r[0], r[1], r[2], r[3]);
    } else {
        *reinterpret_cast<float2*>(o) = make_float2(r[0], r[1]);
    }
}

// ---------------- launch -----------------------------------------------------
extern "C" void kernel_launch(void* const* d_in, const int* in_sizes, int n_in,
                              void* d_out, int out_size) {
    const float* x  = (const float*)d_in[0];
    const int*   ei = (const int*)d_in[1];   // JAX downcasts int64 -> int32
    const float* W1 = (const float*)d_in[2];
    const float* b1 = (const float*)d_in[3];
    const float* W2 = (const float*)d_in[4];
    const float* b2 = (const float*)d_in[5];
    float* out = (float*)d_out;

    const int M = in_sizes[0] / 128;  // 100000 nodes
    const int E = in_sizes[1] / 2;    // 1600000 edges

    float *g1, *h1, *g2;
    cudaGetSymbolAddress((void**)&g1, d_g1);
    cudaGetSymbolAddress((void**)&h1, d_h1);
    cudaGetSymbolAddress((void**)&g2, d_g2);

    // CSR build (shared by both layers)
    k_zero <<<(M + 255) / 256, 256>>>(M);
    k_count<<<(E + 255) / 256, 256>>>(ei, E);
    k_scan <<<1, 1024>>>(M);
    k_fill <<<(E + 255) / 256, 256>>>(ei, E);

    // layer 1: g1 = x@W1 ; h1 = relu(dinv*(gather_w + dinv*self) + b1)
    k_gemm<128, 8><<<(M + 127) / 128, 256>>>(x, W1, g1, M);
    k_agg<128><<<((M * 32) + 255) / 256, 256>>>(g1, b1, h1, M);

    // layer 2: g2 = h1@W2 ; out = relu(dinv*(gather_w + dinv*self) + b2)
    k_gemm<64, 4><<<(M + 127) / 128, 256>>>(h1, W2, g2, M);
    k_agg<64><<<((M * 32) + 255) / 256, 256>>>(g2, b2, out, M);
}